// round 10
// baseline (speedup 1.0000x reference)
#include <cuda_runtime.h>

#define B_ 16
#define D_ 16
#define H_ 288
#define W_ 512
#define N_ (H_*W_)   // 147456
#define L_ 17
#define CH_ 64       // chunks along N for k3 -> 2304 px/block

// persistent scratch (re-zeroed every launch: graph replays reuse it)
__device__ float g_sums[B_][L_][D_];
__device__ float g_cnt[B_][L_];
__device__ float g_means[B_][L_][D_];
__device__ float g_w[B_][L_];

// ---------------------------------------------------------------- kernel 0
__global__ void k0_zero(float* out) {
    int t = blockIdx.x * blockDim.x + threadIdx.x;
    int stride = gridDim.x * blockDim.x;
    if (t == 0) out[0] = 0.f;
    float* s = &g_sums[0][0][0];
    for (int i = t; i < B_*L_*D_; i += stride) s[i] = 0.f;
    float* c = &g_cnt[0][0];
    for (int i = t; i < B_*L_; i += stride) c[i] = 0.f;
}

// ---------------------------------------------------------------- kernel 1
// Per-label sums + counts via per-THREAD indexed smem accumulators.
// Block = (32 lanes, 8 warps); warp w owns dims 2w, 2w+1.
// KEY LAYOUT: acc[chain][warp][label][lane] -> lane l always hits bank l
// (conflict degree == 1 for ANY label pattern). 4 chains (2 per dim) halve
// the serialized LDS->FADD->STS alias-chain depth.
// 8 px/thread/iter, 6 front-batched LDG.128 + depth-1 prefetch.
__global__ void __launch_bounds__(256) k1_sums(const float* __restrict__ emb,
                                               const int* __restrict__ seg) {
    __shared__ float ac[4][8][L_][32];   // 69.6 KB

    const int b    = blockIdx.y;
    const int lane = threadIdx.x;
    const int w    = threadIdx.y;
    const int chunk = N_ / 32;                     // gridDim.x == 32 -> 4608
    const int lo    = blockIdx.x * chunk;
    const int ITERS = chunk / 256;                 // 18 (256 px per warp-iter)

    // thread-private bank-owned slots (no syncs needed anywhere)
    float* __restrict__ p0a = &ac[0][w][0][lane];
    float* __restrict__ p0b = &ac[1][w][0][lane];
    float* __restrict__ p1a = &ac[2][w][0][lane];
    float* __restrict__ p1b = &ac[3][w][0][lane];
#pragma unroll
    for (int s = 0; s < L_; s++) {
        p0a[s*32] = 0.f; p0b[s*32] = 0.f; p1a[s*32] = 0.f; p1b[s*32] = 0.f;
    }

    const float* __restrict__ e0 = emb + ((size_t)b * D_ + 2 * w) * N_;
    const float* __restrict__ e1 = e0 + N_;
    const int*   __restrict__ sp = seg + (size_t)b * N_;

    int cnt[16];
#pragma unroll
    for (int l = 0; l < 16; l++) cnt[l] = 0;

    // depth-1 prefetch: 6 LDG.128 per stage, two dense 128-px groups
    int nA = lo + lane * 4;
    int4   sAx = *(const int4*)(sp + nA);
    int4   sAy = *(const int4*)(sp + nA + 128);
    float4 pA0 = *(const float4*)(e0 + nA);
    float4 pA1 = *(const float4*)(e0 + nA + 128);
    float4 qA0 = *(const float4*)(e1 + nA);
    float4 qA1 = *(const float4*)(e1 + nA + 128);

    for (int it = 0; it < ITERS; ++it) {
        int nn = (it + 1 < ITERS) ? (lo + (it + 1) * 256 + lane * 4) : nA;
        int4   sBx = *(const int4*)(sp + nn);
        int4   sBy = *(const int4*)(sp + nn + 128);
        float4 pB0 = *(const float4*)(e0 + nn);
        float4 pB1 = *(const float4*)(e0 + nn + 128);
        float4 qB0 = *(const float4*)(e1 + nn);
        float4 qB1 = *(const float4*)(e1 + nn + 128);

        // 4 independent accumulate chains, depth 4 each, conflict-free banks
        p0a[sAx.x * 32] += pA0.x;   p1a[sAx.x * 32] += qA0.x;
        p0b[sAx.y * 32] += pA0.y;   p1b[sAx.y * 32] += qA0.y;
        p0a[sAx.z * 32] += pA0.z;   p1a[sAx.z * 32] += qA0.z;
        p0b[sAx.w * 32] += pA0.w;   p1b[sAx.w * 32] += qA0.w;
        p0a[sAy.x * 32] += pA1.x;   p1a[sAy.x * 32] += qA1.x;
        p0b[sAy.y * 32] += pA1.y;   p1b[sAy.y * 32] += qA1.y;
        p0a[sAy.z * 32] += pA1.z;   p1a[sAy.z * 32] += qA1.z;
        p0b[sAy.w * 32] += pA1.w;   p1b[sAy.w * 32] += qA1.w;

        // rotating count warp: every iteration counted exactly once
        if (((it - w) & 7) == 0) {
#pragma unroll
            for (int l = 1; l <= 16; l++)
                cnt[l-1] += (sAx.x == l) + (sAx.y == l) + (sAx.z == l) + (sAx.w == l)
                          + (sAy.x == l) + (sAy.y == l) + (sAy.z == l) + (sAy.w == l);
        }

        sAx = sBx; sAy = sBy;
        pA0 = pB0; pA1 = pB1; qA0 = qB0; qA1 = qB1;
    }

    // merge chains, reduce across the warp, commit via atomics
#pragma unroll
    for (int s = 1; s < L_; s++) {
        float v0 = p0a[s*32] + p0b[s*32];
        float v1 = p1a[s*32] + p1b[s*32];
#pragma unroll
        for (int off = 16; off >= 1; off >>= 1) {
            v0 += __shfl_xor_sync(0xffffffffu, v0, off);
            v1 += __shfl_xor_sync(0xffffffffu, v1, off);
        }
        if (lane == 0) {
            atomicAdd(&g_sums[b][s][2 * w],     v0);
            atomicAdd(&g_sums[b][s][2 * w + 1], v1);
        }
    }
#pragma unroll
    for (int l = 0; l < 16; l++) {
        int c = cnt[l];
#pragma unroll
        for (int off = 16; off >= 1; off >>= 1)
            c += __shfl_xor_sync(0xffffffffu, c, off);
        if (lane == 0 && c > 0) atomicAdd(&g_cnt[b][l+1], (float)c);
    }
}

// ---------------------------------------------------------------- kernel 2
// Finalize means/weights + pairwise push (distance) term. Single block.
__global__ void k2_mid(float* out) {
    __shared__ int   pres[B_][L_];
    __shared__ float nlsh[B_];
    __shared__ float red[512];
    const int tid = threadIdx.x;

    for (int idx = tid; idx < B_*L_; idx += 512) {
        int b = idx / L_, l = idx % L_;
        pres[b][l] = (l != 0 && g_cnt[b][l] > 0.f) ? 1 : 0;
    }
    __syncthreads();
    if (tid < B_) {
        int nl = 0;
        for (int l = 0; l < L_; l++) nl += pres[tid][l];
        nlsh[tid] = (float)nl;
    }
    __syncthreads();

    for (int idx = tid; idx < B_*L_*D_; idx += 512) {
        int b = idx / (L_*D_);
        int l = (idx / D_) % L_;
        int d = idx % D_;
        float c = fmaxf(g_cnt[b][l], 1.f);
        g_means[b][l][d] = g_sums[b][l][d] / c;
    }
    for (int idx = tid; idx < B_*L_; idx += 512) {
        int b = idx / L_, l = idx % L_;
        float c  = fmaxf(g_cnt[b][l], 1.f);
        float nl = fmaxf(nlsh[b], 1.f);
        g_w[b][l] = pres[b][l] ? (1.f / (c * nl * (float)B_)) : 0.f;
    }
    __syncthreads();   // g_means visible block-wide

    float acc = 0.f;
    for (int idx = tid; idx < B_*L_*L_; idx += 512) {
        int b = idx / (L_*L_);
        int i = (idx / L_) % L_;
        int j = idx % L_;
        if (i != j && pres[b][i] && pres[b][j]) {
            float nl = nlsh[b];
            if (nl > 1.f) {
                float ss = 0.f;
#pragma unroll
                for (int d = 0; d < D_; d++) {
                    float dm = g_means[b][i][d] - g_means[b][j][d];
                    ss = fmaf(dm, dm, ss);
                }
                float dist = sqrtf(ss);
                float p = fmaxf(1.5f - dist, 0.f);
                float denom = fmaxf(nl * (nl - 1.f), 1.f);
                acc += (p * p) / denom * 0.5f / (float)B_;
            }
        }
    }
    red[tid] = acc;
    __syncthreads();
    for (int s = 256; s > 0; s >>= 1) {
        if (tid < s) red[tid] += red[tid + s];
        __syncthreads();
    }
    if (tid == 0) atomicAdd(out, red[0]);
}

// ---------------------------------------------------------------- kernel 3
// Variance (pull) term, pre-weighted so it sums directly into the loss.
// 4 pixels/thread via float4/int4; block 288 -> exactly 2 iterations.
__global__ void __launch_bounds__(288) k3_var(const float* __restrict__ emb,
                                              const int* __restrict__ seg,
                                              float* out) {
    const int b = blockIdx.y;
    __shared__ float sm_m[D_][L_];   // [d][l]: 17-float stride, conflict-free
    __shared__ float sm_w[L_];
    __shared__ float wsum[16];
    const int tid = threadIdx.x;

    for (int idx = tid; idx < D_*L_; idx += 288) {
        int d = idx / L_, l = idx % L_;
        sm_m[d][l] = g_means[b][l][d];
    }
    if (tid < L_) sm_w[tid] = g_w[b][tid];
    if (tid < 16) wsum[tid] = 0.f;
    __syncthreads();

    const int chunk = N_ / CH_;      // 2304 = 2 * 288 * 4
    const int lo    = blockIdx.x * chunk;
    const float* __restrict__ e  = emb + (size_t)b * D_ * N_;
    const int* __restrict__   sp = seg + (size_t)b * N_;

    float acc = 0.f;
#pragma unroll
    for (int half = 0; half < 2; half++) {
        int n = lo + half * (288 * 4) + tid * 4;
        int4 s4 = *(const int4*)(sp + n);
        float4 v[D_];
#pragma unroll
        for (int d = 0; d < D_; d++)
            v[d] = *(const float4*)(e + (size_t)d * N_ + n);

#define PXV(S, COMP)                                                           \
        {                                                                      \
            int s = (S);                                                       \
            float w = sm_w[s];                                                 \
            float ss = 0.f;                                                    \
            _Pragma("unroll")                                                  \
            for (int d = 0; d < D_; d++) {                                     \
                float df = v[d].COMP - sm_m[d][s];                             \
                ss = fmaf(df, df, ss);                                         \
            }                                                                  \
            float nrm = sqrtf(fmaxf(ss, 1e-12f));                              \
            float t = fmaxf(nrm - 0.5f, 0.f);                                  \
            acc = fmaf(w, t * t, acc);                                         \
        }
        PXV(s4.x, x); PXV(s4.y, y); PXV(s4.z, z); PXV(s4.w, w);
#undef PXV
    }
#pragma unroll
    for (int off = 16; off >= 1; off >>= 1)
        acc += __shfl_xor_sync(0xffffffffu, acc, off);
    if ((tid & 31) == 0) wsum[tid >> 5] = acc;
    __syncthreads();
    if (tid < 16) {
        float a = wsum[tid];
#pragma unroll
        for (int off = 8; off >= 1; off >>= 1)
            a += __shfl_xor_sync(0xffffu, a, off);
        if (tid == 0) atomicAdd(out, a);
    }
}

// ---------------------------------------------------------------- launch
extern "C" void kernel_launch(void* const* d_in, const int* in_sizes, int n_in,
                              void* d_out, int out_size) {
    const float* emb = (const float*)d_in[0];
    const int*   seg = (const int*)d_in[1];
    float*       out = (float*)d_out;

    k0_zero<<<8, 256>>>(out);

    dim3 g1(32, B_), b1(32, 8);
    k1_sums<<<g1, b1>>>(emb, seg);

    k2_mid<<<1, 512>>>(out);

    dim3 g3(CH_, B_);
    k3_var<<<g3, 288>>>(emb, seg, out);
}